// round 10
// baseline (speedup 1.0000x reference)
#include <cuda_runtime.h>
#include <cuda_fp16.h>
#include <cuda_pipeline.h>
#include <cstdint>

// ---------------- problem constants ----------------
#define B_SZ        8
#define L_SZ        1048576
#define KWIN        500
#define T_WIN       2097            // (L-K)/K + 1
#define TILES_PER_B 17              // ceil(2097/128)
#define NTILES      (B_SZ * TILES_PER_B)   // 136
#define NCHUNK      125             // k32 chunks per tile
#define NTASK       (NTILES * NCHUNK)      // 17000
#define GRID_MAIN   148             // persistent, one CTA per SM
#define OUT_DESCALE (1.0f / 16384.0f)  // C holds scaled products: 2^14 x true

// 2-term compensated fp16: C = Ah*R + P*Q
//   R = fl16(31/32 * B), rB = 31/32*B - R, Q = fl16(B/32 + rB)
//   Ah = fl16(A),        P  = fl16(Ah + 32*(A - Ah))

// smem byte offsets
#define OFF_EMBH   0u               // 257 * uint4 (fp16 Ah pairs)
#define OFF_EMBP   4112u            // 257 * uint4 (fp16 P pairs)
#define OFF_BUF    8224u
#define SZ_AH      8192u            // [2 steps][8 mt][32 lanes][4 regs] u32 (lane-swizzled)
#define SZ_AP      8192u
#define SZ_BR      16384u           // [2 steps][32 nt][32 lanes][2 regs] u32
#define SZ_BQ      16384u
#define BUF_SZ     (SZ_AH + SZ_AP + SZ_BR + SZ_BQ)   // 49152
#define OFF_AH(s)  (OFF_BUF + (s)*BUF_SZ)
#define OFF_AP(s)  (OFF_AH(s) + SZ_AH)
#define OFF_BR(s)  (OFF_AP(s) + SZ_AP)
#define OFF_BQ(s)  (OFF_BR(s) + SZ_BR)
#define SMEM_ALLOC (OFF_BUF + 2u * BUF_SZ)   // 106528

// ---------------- persistent device scratch ----------------
__device__ __align__(16) unsigned g_br[125 * 4096];   // R frags, k16 frag order per chunk
__device__ __align__(16) unsigned g_bq[125 * 4096];   // Q frags, k16 frag order per chunk
__device__ __align__(16) uint4 g_embh[257];           // Ah pairs e01,e23,e45,e67
__device__ __align__(16) uint4 g_embp[257];           // P  pairs
__device__ __align__(16) float g_ctile[NTILES * 128 * 256];  // 17.8MB partial-C buffer
__device__ float g_pooled[B_SZ * 128];

// ---------------- helpers ----------------
__device__ __forceinline__ float wval(const float* w1, const float* w2, int o, int k) {
    const int kp = k >> 3, e = k & 7;
    const float* w = (o < 128) ? w1 : w2;
    return w[(o & 127) * 4000 + e * 500 + kp] * 128.0f;   // pre-scaled by 2^7
}
__device__ __forceinline__ unsigned pack_h2(float a, float b) {
    __half h0 = __float2half_rn(a), h1 = __float2half_rn(b);
    return ((unsigned)__half_as_ushort(h1) << 16) | __half_as_ushort(h0);
}
__device__ __forceinline__ float bRval(float v) {          // fl16(31/32 v) as float
    return __half2float(__float2half_rn(v * 0.96875f));
}
__device__ __forceinline__ float bQval(float v) {          // B/32 + residual of R
    const float rB = v * 0.96875f - bRval(v);
    return v * 0.03125f + rB;                              // rounded once in pack_h2
}
__device__ __forceinline__ void hmma16816(float* c, uint4 a, uint2 b) {
    asm volatile("mma.sync.aligned.m16n8k16.row.col.f32.f16.f16.f32 "
        "{%0,%1,%2,%3}, {%4,%5,%6,%7}, {%8,%9}, {%0,%1,%2,%3};"
        : "+f"(c[0]), "+f"(c[1]), "+f"(c[2]), "+f"(c[3])
        : "r"(a.x), "r"(a.y), "r"(a.z), "r"(a.w), "r"(b.x), "r"(b.y));
}

// ---------------- prep: operand factories + C-buffer zero ----------------
#define ZBLK  4352                  // 4352*1024 = 4456448 = 136*128*256
__global__ void malconv_prep_kernel(const float* __restrict__ w1, const float* __restrict__ w2,
                                    const float* __restrict__ emb)
{
    const int bid = blockIdx.x, tid = threadIdx.x;
    if (bid < 2000) {                                   // BR+BQ in one pass, k16 frag order
        const int u = bid * 256 + tid;
        const int reg = u & 1, lane = (u >> 1) & 31, nt = (u >> 6) & 31;
        const int step = (u >> 11) & 1, ch = u >> 12;
        const int g = lane >> 2, t = lane & 3;
        const int o = nt * 8 + g;
        const int k0 = ch * 32 + step * 16 + reg * 8 + t * 2;
        const float v0 = wval(w1, w2, o, k0), v1 = wval(w1, w2, o, k0 + 1);
        g_br[u] = pack_h2(bRval(v0), bRval(v1));
        g_bq[u] = pack_h2(bQval(v0), bQval(v1));
    } else if (bid < 2000 + ZBLK) {                     // zero g_ctile
        const int idx = (bid - 2000) * 1024 + tid * 4;
        *(float4*)(g_ctile + idx) = make_float4(0.f, 0.f, 0.f, 0.f);
    } else {                                            // emb tables + pooled zero
        for (int v = tid; v < 257; v += 256) {
            float a[8], ah[8], p[8];
            unsigned hp[4], pp[4];
#pragma unroll
            for (int e = 0; e < 8; e++) {
                a[e]  = emb[v * 8 + e] * 128.0f;
                ah[e] = __half2float(__float2half_rn(a[e]));
                p[e]  = ah[e] + 32.0f * (a[e] - ah[e]);
            }
#pragma unroll
            for (int q = 0; q < 4; q++) {
                hp[q] = pack_h2(ah[2 * q], ah[2 * q + 1]);
                pp[q] = pack_h2(p[2 * q],  p[2 * q + 1]);
            }
            g_embh[v] = make_uint4(hp[0], hp[1], hp[2], hp[3]);
            g_embp[v] = make_uint4(pp[0], pp[1], pp[2], pp[3]);
        }
        for (int i = tid; i < B_SZ * 128; i += 256) g_pooled[i] = 0.0f;
    }
}

// ---------------- main: persistent balanced conv GEMM ----------------
__global__ void __launch_bounds__(256, 1)
malconv_main_kernel(const int* __restrict__ x)
{
    extern __shared__ __align__(16) char sb[];
    const int tid  = threadIdx.x;
    const int lane = tid & 31;
    const int wid  = tid >> 5;

    // tables -> smem (once)
    uint4* embh = (uint4*)(sb + OFF_EMBH);
    uint4* embp = (uint4*)(sb + OFF_EMBP);
    for (int i = tid; i < 257; i += 256) { embh[i] = g_embh[i]; embp[i] = g_embp[i]; }
    __syncthreads();

    // A-fill role constants (tile-independent)
    const int arow = tid >> 1, h = tid & 1;
    const int mtile = arow >> 4;
    const int g     = arow & 15;
    const int glow  = g & 7, ghi = g >> 3;
    const int so    = glow >> 1;                 // store-side lane swizzle

    // warp tiling: 8 warps = 2(M) x 4(N); warp tile 64x64
    const int wn = wid & 3, wm = wid >> 2;
    const int sl = lane ^ ((lane >> 3) & 3);     // load-side swizzled lane
    const int grp = lane >> 2, tig = lane & 3;

    int task = (blockIdx.x * NTASK) / GRID_MAIN;
    const int task_end = ((blockIdx.x + 1) * NTASK) / GRID_MAIN;

    while (task < task_end) {
        const int tile = task / NCHUNK;
        const int c0   = task % NCHUNK;
        int c1 = c0 + (task_end - task); if (c1 > NCHUNK) c1 = NCHUNK;
        task += c1 - c0;

        const int bidx = tile / TILES_PER_B;
        const int tt   = tile % TILES_PER_B;
        const int t0   = tt * 128;
        int trow = t0 + arow; if (trow >= T_WIN) trow = T_WIN - 1;
        const int* xrow = x + (size_t)bidx * L_SZ + (size_t)trow * KWIN + 2 * h;

        // A-fill lambda (lane-swizzled fragment order)
        auto fill_A = [&](int buf, int2 xc) {
            unsigned* AHp = (unsigned*)(sb + OFF_AH(buf));
            unsigned* APp = (unsigned*)(sb + OFF_AP(buf));
#pragma unroll
            for (int i = 0; i < 2; i++) {
                const int v = i ? xc.y : xc.x;
                const uint4 eh = embh[v];
                const uint4 ep = embp[v];
                const int base = ((h * 8 + mtile) * 32 + glow * 4) * 4 + (ghi + 2 * i);
                AHp[base + 4 * (0 ^ so)] = eh.x;
                AHp[base + 4 * (1 ^ so)] = eh.y;
                AHp[base + 4 * (2 ^ so)] = eh.z;
                AHp[base + 4 * (3 ^ so)] = eh.w;
                APp[base + 4 * (0 ^ so)] = ep.x;
                APp[base + 4 * (1 ^ so)] = ep.y;
                APp[base + 4 * (2 ^ so)] = ep.z;
                APp[base + 4 * (3 ^ so)] = ep.w;
            }
        };

        float acc[4][8][4];
#pragma unroll
        for (int a = 0; a < 4; a++)
#pragma unroll
            for (int b = 0; b < 8; b++)
#pragma unroll
                for (int j = 0; j < 4; j++) acc[a][b][j] = 0.0f;

        // ---- segment prologue: B(c0) + A(c0) ----
        {
            const int s0 = c0 & 1;
            const unsigned* br = g_br + (size_t)c0 * 4096;
            const unsigned* bq = g_bq + (size_t)c0 * 4096;
#pragma unroll
            for (int i = 0; i < 8; i++) {
                if (i < 4) {
                    const int q = tid + i * 256;
                    __pipeline_memcpy_async(sb + OFF_BR(s0) + q * 16, br + q * 4, 16);
                } else {
                    const int q = tid + (i - 4) * 256;
                    __pipeline_memcpy_async(sb + OFF_BQ(s0) + q * 16, bq + q * 4, 16);
                }
            }
            __pipeline_commit();
        }
        int2 xv = *(const int2*)(xrow + c0 * 4);
        fill_A(c0 & 1, xv);
        if (c0 + 1 < c1) xv = *(const int2*)(xrow + (c0 + 1) * 4);
        __pipeline_wait_prior(0);
        __syncthreads();

        // ---- chunk loop ----
        for (int c = c0; c < c1; ++c) {
            const int s = c & 1;

            // concurrent with MMA(c): fill A(c+1), launch B(c+1)
            if (c + 1 < c1) {
                fill_A(s ^ 1, xv);
                if (c + 2 < c1) xv = *(const int2*)(xrow + (c + 2) * 4);
                const int ns = s ^ 1;
                const unsigned* br = g_br + (size_t)(c + 1) * 4096;
                const unsigned* bq = g_bq + (size_t)(c + 1) * 4096;
#pragma unroll
                for (int i = 0; i < 8; i++) {
                    if (i < 4) {
                        const int q = tid + i * 256;
                        __pipeline_memcpy_async(sb + OFF_BR(ns) + q * 16, br + q * 4, 16);
                    } else {
                        const int q = tid + (i - 4) * 256;
                        __pipeline_memcpy_async(sb + OFF_BQ(ns) + q * 16, bq + q * 4, 16);
                    }
                }
                __pipeline_commit();
            }

            // MMA on chunk c: 4 HMMA per 16x8 subtile
            const unsigned* AHp = (const unsigned*)(sb + OFF_AH(s));
            const unsigned* APp = (const unsigned*)(sb + OFF_AP(s));
            const unsigned* BRp = (const unsigned*)(sb + OFF_BR(s));
            const unsigned* BQp = (const unsigned*)(sb + OFF_BQ(s));
#pragma unroll
            for (int mt = 0; mt < 4; mt++) {
                const int MT = wm * 4 + mt;
                const uint4 ah0 = *(const uint4*)(AHp + ((0 + MT) * 32 + sl) * 4);
                const uint4 ah1 = *(const uint4*)(AHp + ((8 + MT) * 32 + sl) * 4);
                const uint4 ap0 = *(const uint4*)(APp + ((0 + MT) * 32 + sl) * 4);
                const uint4 ap1 = *(const uint4*)(APp + ((8 + MT) * 32 + sl) * 4);
#pragma unroll
                for (int nt = 0; nt < 8; nt++) {
                    const int NT = wn * 8 + nt;
                    const uint2 br0 = *(const uint2*)(BRp + ((0  + NT) * 32 + lane) * 2);
                    const uint2 br1 = *(const uint2*)(BRp + ((32 + NT) * 32 + lane) * 2);
                    const uint2 bq0 = *(const uint2*)(BQp + ((0  + NT) * 32 + lane) * 2);
                    const uint2 bq1 = *(const uint2*)(BQp + ((32 + NT) * 32 + lane) * 2);
                    float* C = acc[mt][nt];
                    hmma16816(C, ah0, br0);      // Ah * R
                    hmma16816(C, ah1, br1);
                    hmma16816(C, ap0, bq0);      // P * Q
                    hmma16816(C, ap1, bq1);
                }
            }

            if (c + 1 < c1) __pipeline_wait_prior(0);
            __syncthreads();
        }

        // ---- flush partial accumulators to gmem C buffer ----
        float* ct = g_ctile + (size_t)tile * 32768;
#pragma unroll
        for (int mt = 0; mt < 4; mt++)
#pragma unroll
            for (int nt = 0; nt < 8; nt++)
#pragma unroll
                for (int j = 0; j < 4; j++) {
                    const int row = wm * 64 + mt * 16 + grp + 8 * (j >> 1);
                    const int col = wn * 64 + nt * 8 + 2 * tig + (j & 1);
                    atomicAdd(ct + row * 256 + col, acc[mt][nt][j]);
                }
    }
}

// ---------------- gate + maxpool over C buffer ----------------
__global__ void malconv_gatemax_kernel(const float* __restrict__ b1, const float* __restrict__ b2)
{
    const int tile = blockIdx.x, tid = threadIdx.x;     // 136 x 256
    const int bidx = tile / TILES_PER_B;
    const int t0   = (tile % TILES_PER_B) * 128;
    const int o = tid & 127, half = tid >> 7;
    int rend = T_WIN - t0; if (rend > 128) rend = 128;
    const int r0 = half * 64;
    int r1 = r0 + 64; if (r1 > rend) r1 = rend;
    const float b1v = b1[o], b2v = b2[o];
    const float* ct = g_ctile + (size_t)tile * 32768;
    float m = 0.0f;
    for (int r = r0; r < r1; r++) {
        const float c1 = ct[r * 256 + o]       * OUT_DESCALE + b1v;
        const float c2 = ct[r * 256 + o + 128] * OUT_DESCALE + b2v;
        const float gg = fmaxf(c1, 0.0f) * (1.0f / (1.0f + __expf(-c2)));
        m = fmaxf(m, gg);
    }
    atomicMax((int*)(g_pooled + bidx * 128 + o), __float_as_int(m));  // m >= 0
}

// ---------------- dense head ----------------
__global__ void malconv_head_kernel(const float* __restrict__ wd1, const float* __restrict__ bd1,
                                    const float* __restrict__ wd2, const float* __restrict__ bd2,
                                    float* __restrict__ out)
{
    __shared__ float psh[B_SZ * 128];
    __shared__ float hsh[B_SZ * 128];
    const int tid = threadIdx.x;                   // 1024 threads
    psh[tid] = g_pooled[tid];
    __syncthreads();
    const int b = tid >> 7, j = tid & 127;
    float acc = bd1[j];
    const float* wr = wd1 + j * 128;
#pragma unroll 8
    for (int o = 0; o < 128; o++) acc += psh[b * 128 + o] * wr[o];
    hsh[tid] = fmaxf(acc, 0.0f);
    __syncthreads();
    if (tid < B_SZ) {
        float a2 = bd2[0];
#pragma unroll 8
        for (int jj = 0; jj < 128; jj++) a2 += hsh[tid * 128 + jj] * wd2[jj];
        out[tid] = 1.0f / (1.0f + __expf(-a2));
    }
}

// ---------------- launch ----------------
extern "C" void kernel_launch(void* const* d_in, const int* in_sizes, int n_in,
                              void* d_out, int out_size) {
    (void)in_sizes; (void)n_in; (void)out_size;
    const int*   x   = (const int*)d_in[0];
    const float* emb = (const float*)d_in[1];
    const float* w1  = (const float*)d_in[2];
    const float* b1  = (const float*)d_in[3];
    const float* w2  = (const float*)d_in[4];
    const float* b2  = (const float*)d_in[5];
    const float* wd1 = (const float*)d_in[6];
    const float* bd1 = (const float*)d_in[7];
    const float* wd2 = (const float*)d_in[8];
    const float* bd2 = (const float*)d_in[9];
    float* out = (float*)d_out;

    cudaFuncSetAttribute(malconv_main_kernel,
                         cudaFuncAttributeMaxDynamicSharedMemorySize, (int)SMEM_ALLOC);

    malconv_prep_kernel<<<2000 + ZBLK + 1, 256>>>(w1, w2, emb);
    malconv_main_kernel<<<GRID_MAIN, 256, SMEM_ALLOC>>>(x);
    malconv_gatemax_kernel<<<NTILES, 256>>>(b1, b2);
    malconv_head_kernel<<<1, 1024>>>(wd1, bd1, wd2, bd2, out);
}

// round 11
// speedup vs baseline: 1.3200x; 1.3200x over previous
#include <cuda_runtime.h>
#include <cuda_fp16.h>
#include <cuda_pipeline.h>
#include <cstdint>

// ---------------- problem constants ----------------
#define B_SZ        8
#define L_SZ        1048576
#define KWIN        500
#define T_WIN       2097            // (L-K)/K + 1
#define TILES_PER_B 17              // ceil(2097/128)
#define GRID_MAIN   (B_SZ * TILES_PER_B)   // 136
#define NCHUNK      125             // 500 positions / 4 per chunk (K-chunk = 32)
#define OUT_DESCALE (1.0f / 16384.0f)  // C holds scaled products: 2^14 x true

// 2-term compensated fp16: C = Ah*R + P*Q
//   R = fl16(31/32 * B), rB = 31/32*B - R, Q = fl16(B/32 + rB)
//   Ah = fl16(A),        P  = fl16(Ah + 32*(A - Ah))

// smem byte offsets (main kernel)
#define OFF_EMBH   0u               // 257 * uint4 (fp16 Ah pairs)
#define OFF_EMBP   4112u            // 257 * uint4 (fp16 P pairs)
#define OFF_BUF    8224u
#define SZ_AH      8192u            // [2 steps][8 mt][32 lanes][4 regs] u32 (lane-swizzled)
#define SZ_AP      8192u
#define SZ_BR      16384u           // [2 steps][32 nt][32 lanes][2 regs] u32
#define SZ_BQ      16384u
#define BUF_SZ     (SZ_AH + SZ_AP + SZ_BR + SZ_BQ)   // 49152
#define OFF_AH(s)  (OFF_BUF + (s)*BUF_SZ)
#define OFF_AP(s)  (OFF_AH(s) + SZ_AH)
#define OFF_BR(s)  (OFF_AP(s) + SZ_AP)
#define OFF_BQ(s)  (OFF_BR(s) + SZ_BR)
#define OFF_GAT    OFF_BUF          // epilogue scratch 128*260*4 = 133120
#define SMEM_ALLOC (OFF_BUF + 128u * 260u * 4u)   // 141344

// head kernel smem: wdt[128*129] + psh[1024] + hsh[1024] + wsh[128]
#define HEAD_SMEM  ((128 * 129 + 1024 + 1024 + 128) * 4)

// ---------------- persistent device scratch ----------------
__device__ __align__(16) unsigned g_br[125 * 4096];   // R frags, k16 frag order per chunk
__device__ __align__(16) unsigned g_bq[125 * 4096];   // Q frags, k16 frag order per chunk
__device__ __align__(16) uint4 g_embh[257];           // Ah pairs e01,e23,e45,e67
__device__ __align__(16) uint4 g_embp[257];           // P  pairs
__device__ float g_pooled[B_SZ * 128];

// ---------------- helpers ----------------
__device__ __forceinline__ float wval(const float* w1, const float* w2, int o, int k) {
    const int kp = k >> 3, e = k & 7;
    const float* w = (o < 128) ? w1 : w2;
    return w[(o & 127) * 4000 + e * 500 + kp] * 128.0f;   // pre-scaled by 2^7
}
__device__ __forceinline__ unsigned pack_h2(float a, float b) {
    __half h0 = __float2half_rn(a), h1 = __float2half_rn(b);
    return ((unsigned)__half_as_ushort(h1) << 16) | __half_as_ushort(h0);
}
__device__ __forceinline__ float bRval(float v) {          // fl16(31/32 v) as float
    return __half2float(__float2half_rn(v * 0.96875f));
}
__device__ __forceinline__ float bQval(float v) {          // B/32 + residual of R
    const float rB = v * 0.96875f - bRval(v);
    return v * 0.03125f + rB;                              // rounded once in pack_h2
}
__device__ __forceinline__ void hmma16816(float* c, uint4 a, uint2 b) {
    asm volatile("mma.sync.aligned.m16n8k16.row.col.f32.f16.f16.f32 "
        "{%0,%1,%2,%3}, {%4,%5,%6,%7}, {%8,%9}, {%0,%1,%2,%3};"
        : "+f"(c[0]), "+f"(c[1]), "+f"(c[2]), "+f"(c[3])
        : "r"(a.x), "r"(a.y), "r"(a.z), "r"(a.w), "r"(b.x), "r"(b.y));
}

// ---------------- prep: one-pass BR+BQ factories + tables ----------------
__global__ void malconv_prep_kernel(const float* __restrict__ w1, const float* __restrict__ w2,
                                    const float* __restrict__ emb)
{
    const int bid = blockIdx.x, tid = threadIdx.x;
    if (bid < 2000) {                                   // BR+BQ, k16 frag order
        const int u = bid * 256 + tid;
        const int reg = u & 1, lane = (u >> 1) & 31, nt = (u >> 6) & 31;
        const int step = (u >> 11) & 1, ch = u >> 12;
        const int g = lane >> 2, t = lane & 3;
        const int o = nt * 8 + g;
        const int k0 = ch * 32 + step * 16 + reg * 8 + t * 2;
        const float v0 = wval(w1, w2, o, k0), v1 = wval(w1, w2, o, k0 + 1);
        g_br[u] = pack_h2(bRval(v0), bRval(v1));
        g_bq[u] = pack_h2(bQval(v0), bQval(v1));
    } else {                                            // emb tables + pooled zero
        for (int v = tid; v < 257; v += 256) {
            float a[8], ah[8], p[8];
            unsigned hp[4], pp[4];
#pragma unroll
            for (int e = 0; e < 8; e++) {
                a[e]  = emb[v * 8 + e] * 128.0f;
                ah[e] = __half2float(__float2half_rn(a[e]));
                p[e]  = ah[e] + 32.0f * (a[e] - ah[e]);
            }
#pragma unroll
            for (int q = 0; q < 4; q++) {
                hp[q] = pack_h2(ah[2 * q], ah[2 * q + 1]);
                pp[q] = pack_h2(p[2 * q],  p[2 * q + 1]);
            }
            g_embh[v] = make_uint4(hp[0], hp[1], hp[2], hp[3]);
            g_embp[v] = make_uint4(pp[0], pp[1], pp[2], pp[3]);
        }
        for (int i = tid; i < B_SZ * 128; i += 256) g_pooled[i] = 0.0f;
    }
}

// ---------------- main fused conv GEMM + gate + maxpool ----------------
__global__ void __launch_bounds__(256, 1)
malconv_main_kernel(const int* __restrict__ x,
                    const float* __restrict__ b1, const float* __restrict__ b2)
{
    extern __shared__ __align__(16) char sb[];
    const int tid  = threadIdx.x;
    const int lane = tid & 31;
    const int wid  = tid >> 5;

    const int bidx = blockIdx.x / TILES_PER_B;
    const int tt   = blockIdx.x % TILES_PER_B;
    const int t0   = tt * 128;

    // tables -> smem
    uint4* embh = (uint4*)(sb + OFF_EMBH);
    uint4* embp = (uint4*)(sb + OFF_EMBP);
    for (int i = tid; i < 257; i += 256) { embh[i] = g_embh[i]; embp[i] = g_embp[i]; }

    // A-fill role: 2 threads per row (h = 0/1), 2 conv positions each (p = 2h, 2h+1)
    const int arow = tid >> 1, h = tid & 1;
    int trow = t0 + arow; if (trow >= T_WIN) trow = T_WIN - 1;
    const int* xrow = x + (size_t)bidx * L_SZ + (size_t)trow * KWIN + 2 * h;

    const int mtile = arow >> 4;
    const int g     = arow & 15;
    const int glow  = g & 7, ghi = g >> 3;
    const int so    = glow >> 1;                 // store-side lane swizzle (2 bits)

    // A-fill lambda (lane-swizzled fragment order)
    auto fill_A = [&](int buf, int2 xc) {
        unsigned* AHp = (unsigned*)(sb + OFF_AH(buf));
        unsigned* APp = (unsigned*)(sb + OFF_AP(buf));
#pragma unroll
        for (int i = 0; i < 2; i++) {
            const int v = i ? xc.y : xc.x;
            const uint4 eh = embh[v];
            const uint4 ep = embp[v];
            const int base = ((h * 8 + mtile) * 32 + glow * 4) * 4 + (ghi + 2 * i);
            AHp[base + 4 * (0 ^ so)] = eh.x;
            AHp[base + 4 * (1 ^ so)] = eh.y;
            AHp[base + 4 * (2 ^ so)] = eh.z;
            AHp[base + 4 * (3 ^ so)] = eh.w;
            APp[base + 4 * (0 ^ so)] = ep.x;
            APp[base + 4 * (1 ^ so)] = ep.y;
            APp[base + 4 * (2 ^ so)] = ep.z;
            APp[base + 4 * (3 ^ so)] = ep.w;
        }
    };

    // prologue: cp.async B chunk 0 into buf 0
#pragma unroll
    for (int i = 0; i < 8; i++) {
        if (i < 4) {
            const int q = tid + i * 256;
            __pipeline_memcpy_async(sb + OFF_BR(0) + q * 16, g_br + q * 4, 16);
        } else {
            const int q = tid + (i - 4) * 256;
            __pipeline_memcpy_async(sb + OFF_BQ(0) + q * 16, g_bq + q * 4, 16);
        }
    }
    __pipeline_commit();
    int2 xv = *(const int2*)xrow;                // chunk 0 x-values
    __syncthreads();                             // emb tables ready

    fill_A(0, xv);                               // A(0)
    xv = *(const int2*)(xrow + 4);               // chunk 1 x-values
    __pipeline_wait_prior(0);
    __syncthreads();                             // A(0) + B(0) ready

    // warp tiling: 8 warps = 2(M) x 4(N); warp tile 64x64
    const int wn = wid & 3, wm = wid >> 2;
    const int sl = lane ^ ((lane >> 3) & 3);     // load-side swizzled lane
    float acc[4][8][4];
#pragma unroll
    for (int a = 0; a < 4; a++)
#pragma unroll
        for (int b = 0; b < 8; b++)
#pragma unroll
            for (int j = 0; j < 4; j++) acc[a][b][j] = 0.0f;

    for (int c = 0; c < NCHUNK; ++c) {
        const int s = c & 1;

        // ---- concurrent with MMA(c): fill A(c+1), launch B(c+1) ----
        if (c + 1 < NCHUNK) {
            fill_A(s ^ 1, xv);
            if (c + 2 < NCHUNK) xv = *(const int2*)(xrow + (c + 2) * 4);
            const int ns = s ^ 1;
            const unsigned* br = g_br + (size_t)(c + 1) * 4096;
            const unsigned* bq = g_bq + (size_t)(c + 1) * 4096;
#pragma unroll
            for (int i = 0; i < 8; i++) {
                if (i < 4) {
                    const int q = tid + i * 256;
                    __pipeline_memcpy_async(sb + OFF_BR(ns) + q * 16, br + q * 4, 16);
                } else {
                    const int q = tid + (i - 4) * 256;
                    __pipeline_memcpy_async(sb + OFF_BQ(ns) + q * 16, bq + q * 4, 16);
                }
            }
            __pipeline_commit();
        }

        // ---- MMA on chunk c: 4 HMMA per 16x8 subtile (2 main + 2 correction) ----
        const unsigned* AHp = (const unsigned*)(sb + OFF_AH(s));
        const unsigned* APp = (const unsigned*)(sb + OFF_AP(s));
        const unsigned* BRp = (const unsigned*)(sb + OFF_BR(s));
        const unsigned* BQp = (const unsigned*)(sb + OFF_BQ(s));
#pragma unroll
        for (int mt = 0; mt < 4; mt++) {
            const int MT = wm * 4 + mt;
            const uint4 ah0 = *(const uint4*)(AHp + ((0 + MT) * 32 + sl) * 4);
            const uint4 ah1 = *(const uint4*)(AHp + ((8 + MT) * 32 + sl) * 4);
            const uint4 ap0 = *(const uint4*)(APp + ((0 + MT) * 32 + sl) * 4);
            const uint4 ap1 = *(const uint4*)(APp + ((8 + MT) * 32 + sl) * 4);
#pragma unroll
            for (int nt = 0; nt < 8; nt++) {
                const int NT = wn * 8 + nt;
                const uint2 br0 = *(const uint2*)(BRp + ((0  + NT) * 32 + lane) * 2);
                const uint2 br1 = *(const uint2*)(BRp + ((32 + NT) * 32 + lane) * 2);
                const uint2 bq0 = *(const uint2*)(BQp + ((0  + NT) * 32 + lane) * 2);
                const uint2 bq1 = *(const uint2*)(BQp + ((32 + NT) * 32 + lane) * 2);
                float* C = acc[mt][nt];
                hmma16816(C, ah0, br0);      // Ah * R   (k steps 0,1)
                hmma16816(C, ah1, br1);
                hmma16816(C, ap0, bq0);      // P * Q
                hmma16816(C, ap1, bq1);
            }
        }

        if (c + 1 < NCHUNK) __pipeline_wait_prior(0);
        __syncthreads();                         // next-chunk bufs ready
    }

    // ---- epilogue ----
    float* gat = (float*)(sb + OFF_GAT);                 // [row][o], stride 260
    const int grp = lane >> 2, tig = lane & 3;
#pragma unroll
    for (int mt = 0; mt < 4; mt++)
#pragma unroll
        for (int nt = 0; nt < 8; nt++)
#pragma unroll
            for (int j = 0; j < 4; j++) {
                const int row = wm * 64 + mt * 16 + grp + 8 * (j >> 1);
                const int col = wn * 64 + nt * 8 + 2 * tig + (j & 1);
                gat[row * 260 + col] = acc[mt][nt][j];
            }
    __syncthreads();

    {
        const int o = tid & 127;
        const int half = tid >> 7;
        const float b1v = b1[o], b2v = b2[o];
        int rend = T_WIN - t0; if (rend > 128) rend = 128;
        const int r0 = half * 64;
        int r1 = r0 + 64; if (r1 > rend) r1 = rend;
        float m = 0.0f;
        for (int r = r0; r < r1; r++) {
            const float c1 = gat[r * 260 + o]       * OUT_DESCALE + b1v;
            const float c2 = gat[r * 260 + o + 128] * OUT_DESCALE + b2v;
            const float gg = fmaxf(c1, 0.0f) * (1.0f / (1.0f + __expf(-c2)));
            m = fmaxf(m, gg);
        }
        atomicMax((int*)(g_pooled + bidx * 128 + o), __float_as_int(m));  // m >= 0
    }
}

// ---------------- dense head (coalesced, smem-staged) ----------------
__global__ void malconv_head_kernel(const float* __restrict__ wd1, const float* __restrict__ bd1,
                                    const float* __restrict__ wd2, const float* __restrict__ bd2,
                                    float* __restrict__ out)
{
    extern __shared__ float hs[];
    float* wdt = hs;                       // [o][j], stride 129 (transposed wd1)
    float* psh = hs + 128 * 129;           // pooled [b][o]
    float* hsh = psh + 1024;               // hidden [b][j]
    float* wsh = hsh + 1024;               // wd2 [j]
    const int tid = threadIdx.x;           // 1024 threads

    psh[tid] = g_pooled[tid];
    if (tid < 128) wsh[tid] = wd2[tid];
    // coalesced load + transpose: wd1[j*128+o] -> wdt[o*129+j]
    const float4* w4 = (const float4*)wd1;
#pragma unroll
    for (int i = tid; i < 4096; i += 1024) {
        const float4 v = w4[i];
        const int base = i * 4;            // linear idx = j*128 + o
        const int j = base >> 7;
        const int o = base & 127;
        wdt[(o + 0) * 129 + j] = v.x;
        wdt[(o + 1) * 129 + j] = v.y;
        wdt[(o + 2) * 129 + j] = v.z;
        wdt[(o + 3) * 129 + j] = v.w;
    }
    __syncthreads();

    // h[b][j] = relu(bd1[j] + sum_o pooled[b][o] * wd1[j][o])
    const int b = tid >> 7, j = tid & 127;
    float acc = bd1[j];
    const float* pb = psh + b * 128;
#pragma unroll 16
    for (int o = 0; o < 128; o++) acc += pb[o] * wdt[o * 129 + j];
    hsh[tid] = fmaxf(acc, 0.0f);
    __syncthreads();

    // out[b] = sigmoid(bd2 + sum_j h[b][j]*wd2[j]) -- warp b, shuffle reduce
    const int wrp = tid >> 5, lane = tid & 31;
    if (wrp < 8) {
        float a2 = 0.0f;
#pragma unroll
        for (int q = 0; q < 4; q++) {
            const int jj = lane + q * 32;
            a2 += hsh[wrp * 128 + jj] * wsh[jj];
        }
#pragma unroll
        for (int d = 16; d > 0; d >>= 1) a2 += __shfl_xor_sync(0xFFFFFFFF, a2, d);
        if (lane == 0) out[wrp] = 1.0f / (1.0f + __expf(-(a2 + bd2[0])));
    }
}

// ---------------- launch ----------------
extern "C" void kernel_launch(void* const* d_in, const int* in_sizes, int n_in,
                              void* d_out, int out_size) {
    (void)in_sizes; (void)n_in; (void)out_size;
    const int*   x   = (const int*)d_in[0];
    const float* emb = (const float*)d_in[1];
    const float* w1  = (const float*)d_in[2];
    const float* b1  = (const float*)d_in[3];
    const float* w2  = (const float*)d_in[4];
    const float* b2  = (const float*)d_in[5];
    const float* wd1 = (const float*)d_in[6];
    const float* bd1 = (const float*)d_in[7];
    const float* wd2 = (const float*)d_in[8];
    const float* bd2 = (const float*)d_in[9];
    float* out = (float*)d_out;

    cudaFuncSetAttribute(malconv_main_kernel,
                         cudaFuncAttributeMaxDynamicSharedMemorySize, (int)SMEM_ALLOC);
    cudaFuncSetAttribute(malconv_head_kernel,
                         cudaFuncAttributeMaxDynamicSharedMemorySize, (int)HEAD_SMEM);

    malconv_prep_kernel<<<2001, 256>>>(w1, w2, emb);
    malconv_main_kernel<<<GRID_MAIN, 256, SMEM_ALLOC>>>(x, b1, b2);
    malconv_head_kernel<<<1, 1024, HEAD_SMEM>>>(wd1, bd1, wd2, bd2, out);
}